// round 2
// baseline (speedup 1.0000x reference)
#include <cuda_runtime.h>
#include <math.h>

// Problem constants (fixed by the dataset)
#define NN 10000   // nodes
#define PP 25000   // edge-pairs
#define BB 8       // batch
#define FF 16      // feats
#define MM 32      // MLP width
#define HH 2       // MLP hidden layers
#define TWO_F (2*FF)          // 32
#define NODE_STRIDE (BB*FF)   // 128 floats per node
#define XELEMS (NN*NODE_STRIDE)

// triple node-state buffers, [N][B][F] layout (layer0: 0->1, layer1: 1->2)
__device__ __align__(16) float g_x[3][XELEMS];

// ---------------------------------------------------------------------------
// prep: h [B][N][F] -> g_x[0] [N][B][F]; zero g_x[1], g_x[2].
// one thread per (n,b); f-axis contiguous in both layouts -> float4 x4
__global__ void prep_kernel(const float* __restrict__ h) {
    int idx = blockIdx.x * blockDim.x + threadIdx.x;
    if (idx >= NN * BB) return;
    int n = idx >> 3;          // / BB
    int b = idx & 7;           // % BB
    const float4* s  = (const float4*)(h + (size_t)b * NN * FF + (size_t)n * FF);
    float4* d0 = (float4*)(g_x[0] + (size_t)n * NODE_STRIDE + b * FF);
    float4* d1 = (float4*)(g_x[1] + (size_t)n * NODE_STRIDE + b * FF);
    float4* d2 = (float4*)(g_x[2] + (size_t)n * NODE_STRIDE + b * FF);
    const float4 z = make_float4(0.f, 0.f, 0.f, 0.f);
    #pragma unroll
    for (int j = 0; j < 4; j++) {
        d0[j] = s[j];
        d1[j] = z;
        d2[j] = z;
    }
}

// g_x[2] [N][B][F] -> out [B][N][F]
__global__ void out_kernel(float* __restrict__ out) {
    int idx = blockIdx.x * blockDim.x + threadIdx.x;
    if (idx >= NN * BB) return;
    int n = idx >> 3;
    int b = idx & 7;
    const float4* s = (const float4*)(g_x[2] + (size_t)n * NODE_STRIDE + b * FF);
    float4* d = (float4*)(out + (size_t)b * NN * FF + (size_t)n * FF);
    #pragma unroll
    for (int j = 0; j < 4; j++) d[j] = s[j];
}

// ---------------------------------------------------------------------------
// One warp per edge-pair (edge index PP = the fixed edge with shared weights).
// Lane m owns output column m; 8 batch accumulators in registers; activations
// broadcast from shared via LDS.128; weight columns staged into registers so
// all 32 LDGs of a layer issue back-to-back.
#define WPB 8  // warps per block

__global__ void __launch_bounds__(WPB * 32)
edge_kernel(const float* __restrict__ Wi0,  const float* __restrict__ Wih,
            const float* __restrict__ Wiout,const float* __restrict__ bi0,
            const float* __restrict__ bih,  const float* __restrict__ biout,
            const float* __restrict__ Wf0,  const float* __restrict__ Wfh,
            const float* __restrict__ Wfout,const float* __restrict__ bf0,
            const float* __restrict__ bfh,  const float* __restrict__ bfout,
            const int* __restrict__ src,    const int* __restrict__ dst,
            int layer, int curbuf, int nxtbuf)
{
    __shared__ __align__(16) float smA[WPB][BB][MM];
    __shared__ __align__(16) float smB[WPB][BB][MM];

    const int w    = threadIdx.x >> 5;
    const int lane = threadIdx.x & 31;
    const int e    = blockIdx.x * WPB + w;
    if (e > PP) return;

    const bool fx   = (e == PP);
    const int  eidx = fx ? 2 * PP : e;   // fixed edge is the last entry
    const int  d = dst[eidx];
    const int  s = src[eidx];

    const long Pp = fx ? 1 : PP;
    const long pe = fx ? 0 : e;

    const float* W0   = (fx ? Wf0   : Wi0)   + ((long)layer * Pp + pe) * (TWO_F * MM);
    const float* b0   = (fx ? bf0   : bi0)   + ((long)layer * Pp + pe) * MM;
    const float* Wout = (fx ? Wfout : Wiout) + ((long)layer * Pp + pe) * (MM * FF);
    const float* bout = (fx ? bfout : biout) + ((long)layer * Pp + pe) * FF;
    const float* WhB  = fx ? Wfh : Wih;
    const float* bhB  = fx ? bfh : bih;

    const float* xcur = g_x[curbuf];
    float*       xnxt = g_x[nxtbuf];

    // ---- gather edge input: [B][2F] = concat(x[dst], x[src]) on feature axis
    const float* xd = xcur + (long)d * NODE_STRIDE;
    const float* xs = xcur + (long)s * NODE_STRIDE;
    #pragma unroll
    for (int b = 0; b < BB; b++) {
        smA[w][b][lane] = (lane < FF) ? __ldg(xd + b * FF + lane)
                                      : __ldg(xs + b * FF + (lane - FF));
    }
    __syncwarp();

    float acc[BB];
    float wreg[MM];

    // ---- layer 0: [B,2F] @ [2F,M] + silu
    {
        #pragma unroll
        for (int k = 0; k < TWO_F; k++) wreg[k] = __ldg(W0 + k * MM + lane);
        const float bias = __ldg(b0 + lane);
        #pragma unroll
        for (int b = 0; b < BB; b++) acc[b] = bias;
        #pragma unroll
        for (int b = 0; b < BB; b++) {
            #pragma unroll
            for (int k0 = 0; k0 < TWO_F; k0 += 4) {
                const float4 a = *(const float4*)&smA[w][b][k0];
                acc[b] = fmaf(a.x, wreg[k0 + 0], acc[b]);
                acc[b] = fmaf(a.y, wreg[k0 + 1], acc[b]);
                acc[b] = fmaf(a.z, wreg[k0 + 2], acc[b]);
                acc[b] = fmaf(a.w, wreg[k0 + 3], acc[b]);
            }
        }
        #pragma unroll
        for (int b = 0; b < BB; b++) {
            const float v = acc[b];
            smB[w][b][lane] = v / (1.0f + __expf(-v));
        }
    }
    __syncwarp();

    // ---- hidden layers: [B,M] @ [M,M] + silu, ping-pong smB <-> smA
    float (*cur)[MM] = smB[w];
    float (*nxt)[MM] = smA[w];
    #pragma unroll
    for (int i = 0; i < HH; i++) {
        const float* Wh = WhB + (((long)layer * HH + i) * Pp + pe) * (MM * MM);
        const float* bh = bhB + (((long)layer * HH + i) * Pp + pe) * MM;
        #pragma unroll
        for (int k = 0; k < MM; k++) wreg[k] = __ldg(Wh + k * MM + lane);
        const float bias = __ldg(bh + lane);
        #pragma unroll
        for (int b = 0; b < BB; b++) acc[b] = bias;
        #pragma unroll
        for (int b = 0; b < BB; b++) {
            #pragma unroll
            for (int k0 = 0; k0 < MM; k0 += 4) {
                const float4 a = *(const float4*)&cur[b][k0];
                acc[b] = fmaf(a.x, wreg[k0 + 0], acc[b]);
                acc[b] = fmaf(a.y, wreg[k0 + 1], acc[b]);
                acc[b] = fmaf(a.z, wreg[k0 + 2], acc[b]);
                acc[b] = fmaf(a.w, wreg[k0 + 3], acc[b]);
            }
        }
        #pragma unroll
        for (int b = 0; b < BB; b++) {
            const float v = acc[b];
            nxt[b][lane] = v / (1.0f + __expf(-v));
        }
        __syncwarp();
        float (*t)[MM] = cur; cur = nxt; nxt = t;
    }

    // ---- output layer: [B,M] @ [M,F] ; lanes 0-15 -> batches 0-3, 16-31 -> 4-7
    const int f  = lane & 15;
    const int bg = lane >> 4;
    #pragma unroll
    for (int k = 0; k < MM; k++) wreg[k] = __ldg(Wout + k * FF + f);
    float o[4];
    const float ob = __ldg(bout + f);
    #pragma unroll
    for (int j = 0; j < 4; j++) o[j] = ob;
    #pragma unroll
    for (int j = 0; j < 4; j++) {
        #pragma unroll
        for (int k0 = 0; k0 < MM; k0 += 4) {
            const float4 a = *(const float4*)&cur[bg * 4 + j][k0];
            o[j] = fmaf(a.x, wreg[k0 + 0], o[j]);
            o[j] = fmaf(a.y, wreg[k0 + 1], o[j]);
            o[j] = fmaf(a.z, wreg[k0 + 2], o[j]);
            o[j] = fmaf(a.w, wreg[k0 + 3], o[j]);
        }
    }

    // ---- scatter: +msg to dst, -msg to src (fixed edge: + to dst only)
    float* yd = xnxt + (long)d * NODE_STRIDE;
    float* ys = xnxt + (long)s * NODE_STRIDE;
    #pragma unroll
    for (int j = 0; j < 4; j++) {
        const int b = bg * 4 + j;
        atomicAdd(yd + b * FF + f, o[j]);
        if (!fx) atomicAdd(ys + b * FF + f, -o[j]);
    }
}

// ---------------------------------------------------------------------------
extern "C" void kernel_launch(void* const* d_in, const int* in_sizes, int n_in,
                              void* d_out, int out_size) {
    const float* h     = (const float*)d_in[0];
    const float* Wi0   = (const float*)d_in[1];
    const float* Wih   = (const float*)d_in[2];
    const float* Wiout = (const float*)d_in[3];
    const float* bi0   = (const float*)d_in[4];
    const float* bih   = (const float*)d_in[5];
    const float* biout = (const float*)d_in[6];
    const float* Wf0   = (const float*)d_in[7];
    const float* Wfh   = (const float*)d_in[8];
    const float* Wfout = (const float*)d_in[9];
    const float* bf0   = (const float*)d_in[10];
    const float* bfh   = (const float*)d_in[11];
    const float* bfout = (const float*)d_in[12];
    const int*   src   = (const int*)d_in[13];
    const int*   dst   = (const int*)d_in[14];
    float*       out   = (float*)d_out;

    const int tb = 256;
    const int pblocks = (NN * BB + tb - 1) / tb;
    const int eblocks = (PP + 1 + WPB - 1) / WPB;

    prep_kernel<<<pblocks, tb>>>(h);

    edge_kernel<<<eblocks, WPB * 32>>>(Wi0, Wih, Wiout, bi0, bih, biout,
                                       Wf0, Wfh, Wfout, bf0, bfh, bfout,
                                       src, dst, /*layer=*/0, /*cur=*/0, /*nxt=*/1);

    edge_kernel<<<eblocks, WPB * 32>>>(Wi0, Wih, Wiout, bi0, bih, biout,
                                       Wf0, Wfh, Wfout, bf0, bfh, bfout,
                                       src, dst, /*layer=*/1, /*cur=*/1, /*nxt=*/2);

    out_kernel<<<pblocks, tb>>>(out);
}

// round 3
// speedup vs baseline: 1.3477x; 1.3477x over previous
#include <cuda_runtime.h>
#include <math.h>

// Problem constants (fixed by the dataset)
#define NN 10000   // nodes
#define PP 25000   // edge-pairs
#define BB 8       // batch
#define FF 16      // feats
#define MM 32      // MLP width
#define HH 2       // MLP hidden layers
#define TWO_F (2*FF)          // 32
#define NODE_STRIDE (BB*FF)   // 128 floats per node
#define XELEMS (NN*NODE_STRIDE)

// triple node-state buffers, [N][B][F] layout (layer0: 0->1, layer1: 1->2)
__device__ __align__(16) float g_x[3][XELEMS];

// ---------------------------------------------------------------------------
// f32x2 packed-math helpers (sm_103a)
__device__ __forceinline__ unsigned long long pk2(float x, float y) {
    unsigned long long r;
    asm("mov.b64 %0,{%1,%2};" : "=l"(r) : "f"(x), "f"(y));
    return r;
}
__device__ __forceinline__ void upk2(unsigned long long v, float& x, float& y) {
    asm("mov.b64 {%0,%1},%2;" : "=f"(x), "=f"(y) : "l"(v));
}
__device__ __forceinline__ unsigned long long fma2(unsigned long long a,
                                                   unsigned long long b,
                                                   unsigned long long c) {
    unsigned long long d;
    asm("fma.rn.f32x2 %0,%1,%2,%3;" : "=l"(d) : "l"(a), "l"(b), "l"(c));
    return d;
}
__device__ __forceinline__ float silu_f(float v) { return v / (1.0f + __expf(-v)); }

// ---------------------------------------------------------------------------
// profiler-alignment dummy (places edge_kernel at profiled launch slot)
__global__ void dummy_kernel() {}

// prep: h [B][N][F] -> g_x[0] [N][B][F]; zero g_x[1], g_x[2].
// idx = b*NN + n  => h side fully coalesced; g_x side scatters into L2.
__global__ void prep_kernel(const float* __restrict__ h) {
    int idx = blockIdx.x * blockDim.x + threadIdx.x;
    if (idx >= NN * BB) return;
    int b = idx / NN;
    int n = idx - b * NN;
    const float4* s  = (const float4*)(h + (size_t)b * NN * FF + (size_t)n * FF);
    float4* d0 = (float4*)(g_x[0] + (size_t)n * NODE_STRIDE + b * FF);
    float4* d1 = (float4*)(g_x[1] + (size_t)n * NODE_STRIDE + b * FF);
    float4* d2 = (float4*)(g_x[2] + (size_t)n * NODE_STRIDE + b * FF);
    const float4 z = make_float4(0.f, 0.f, 0.f, 0.f);
    #pragma unroll
    for (int j = 0; j < 4; j++) { d0[j] = s[j]; d1[j] = z; d2[j] = z; }
}

// g_x[2] [N][B][F] -> out [B][N][F]; out side fully coalesced.
__global__ void out_kernel(float* __restrict__ out) {
    int idx = blockIdx.x * blockDim.x + threadIdx.x;
    if (idx >= NN * BB) return;
    int b = idx / NN;
    int n = idx - b * NN;
    const float4* s = (const float4*)(g_x[2] + (size_t)n * NODE_STRIDE + b * FF);
    float4* d = (float4*)(out + (size_t)b * NN * FF + (size_t)n * FF);
    #pragma unroll
    for (int j = 0; j < 4; j++) d[j] = s[j];
}

// ---------------------------------------------------------------------------
// One warp per edge-pair. Activations live in k-major smem [k][b]: the FMA
// loop reads row k (uniform across lanes -> broadcast, conflict-free) as two
// LDS.128, giving 4 packed f32x2 operands. Lane m owns output column m and
// holds 4 packed batch-pair accumulators. Weight loads stay interleaved with
// FMAs (32 coalesced 128B LDG.32 per layer) so ptxas pipelines them.
#define WPB 8  // warps per block

// one MLP layer: [B,32] @ [32,M] + bias, optional silu, k-major in/out
__device__ __forceinline__ void mlp32_layer(const float* __restrict__ W,
                                            const float* __restrict__ bias,
                                            const float (*cur)[BB],
                                            float (*nxt)[BB],
                                            int lane)
{
    const float bv = bias[lane];
    unsigned long long acc2[4];
    #pragma unroll
    for (int j = 0; j < 4; j++) acc2[j] = pk2(bv, bv);
    #pragma unroll
    for (int k = 0; k < MM; k++) {
        const float w = W[k * MM + lane];
        const unsigned long long w2 = pk2(w, w);
        const ulonglong2* row = (const ulonglong2*)cur[k];
        const ulonglong2 r0 = row[0];
        const ulonglong2 r1 = row[1];
        acc2[0] = fma2(r0.x, w2, acc2[0]);
        acc2[1] = fma2(r0.y, w2, acc2[1]);
        acc2[2] = fma2(r1.x, w2, acc2[2]);
        acc2[3] = fma2(r1.y, w2, acc2[3]);
    }
    float s[8];
    #pragma unroll
    for (int j = 0; j < 4; j++) {
        float a, b;
        upk2(acc2[j], a, b);
        s[2 * j]     = silu_f(a);
        s[2 * j + 1] = silu_f(b);
    }
    *(float4*)&nxt[lane][0] = make_float4(s[0], s[1], s[2], s[3]);
    *(float4*)&nxt[lane][4] = make_float4(s[4], s[5], s[6], s[7]);
}

__global__ void __launch_bounds__(WPB * 32)
edge_kernel(const float* __restrict__ Wi0,  const float* __restrict__ Wih,
            const float* __restrict__ Wiout,const float* __restrict__ bi0,
            const float* __restrict__ bih,  const float* __restrict__ biout,
            const float* __restrict__ Wf0,  const float* __restrict__ Wfh,
            const float* __restrict__ Wfout,const float* __restrict__ bf0,
            const float* __restrict__ bfh,  const float* __restrict__ bfout,
            const int* __restrict__ src,    const int* __restrict__ dst,
            int layer, int curbuf, int nxtbuf)
{
    // k-major double-buffered activations: [warp][pp][k][b]
    __shared__ __align__(16) float smX[WPB][2][MM][BB];

    const int w    = threadIdx.x >> 5;
    const int lane = threadIdx.x & 31;
    const int e    = blockIdx.x * WPB + w;
    if (e > PP) return;

    const bool fx   = (e == PP);
    const int  eidx = fx ? 2 * PP : e;   // fixed edge is the last entry
    const int  d = dst[eidx];
    const int  s = src[eidx];

    const long Pp = fx ? 1 : PP;
    const long pe = fx ? 0 : e;

    const float* W0   = (fx ? Wf0   : Wi0)   + ((long)layer * Pp + pe) * (TWO_F * MM);
    const float* b0   = (fx ? bf0   : bi0)   + ((long)layer * Pp + pe) * MM;
    const float* Wout = (fx ? Wfout : Wiout) + ((long)layer * Pp + pe) * (MM * FF);
    const float* bout = (fx ? bfout : biout) + ((long)layer * Pp + pe) * FF;
    const float* WhB  = fx ? Wfh : Wih;
    const float* bhB  = fx ? bfh : bih;

    const float* xcur = g_x[curbuf];
    float*       xnxt = g_x[nxtbuf];

    // ---- gather edge input into k-major smem: lane = k (feature of [x_dst | x_src])
    {
        const float* xd = xcur + (long)d * NODE_STRIDE;
        const float* xs = xcur + (long)s * NODE_STRIDE;
        const float* xg = (lane < FF) ? xd : xs;
        const int f0 = lane & 15;
        float v[BB];
        #pragma unroll
        for (int b = 0; b < BB; b++) v[b] = xg[b * FF + f0];
        *(float4*)&smX[w][0][lane][0] = make_float4(v[0], v[1], v[2], v[3]);
        *(float4*)&smX[w][0][lane][4] = make_float4(v[4], v[5], v[6], v[7]);
    }
    __syncwarp();

    // ---- layer 0 + hidden layers (all are 32 -> 32)
    mlp32_layer(W0, b0, smX[w][0], smX[w][1], lane);
    __syncwarp();
    int cur = 1;
    #pragma unroll
    for (int i = 0; i < HH; i++) {
        const float* Wh = WhB + (((long)layer * HH + i) * Pp + pe) * (MM * MM);
        const float* bh = bhB + (((long)layer * HH + i) * Pp + pe) * MM;
        mlp32_layer(Wh, bh, smX[w][cur], smX[w][cur ^ 1], lane);
        __syncwarp();
        cur ^= 1;
    }

    // ---- output layer: [B,32] @ [32,16]; lanes 0-15 -> batches 0-3, 16-31 -> 4-7
    const int f  = lane & 15;
    const int bg = lane >> 4;
    const float ob = bout[f];
    unsigned long long o2[2] = { pk2(ob, ob), pk2(ob, ob) };
    const float (*A)[BB] = smX[w][cur];
    #pragma unroll
    for (int k = 0; k < MM; k++) {
        const float wv = Wout[k * FF + f];
        const unsigned long long w2 = pk2(wv, wv);
        const ulonglong2 r = *(const ulonglong2*)&A[k][bg * 4];
        o2[0] = fma2(r.x, w2, o2[0]);
        o2[1] = fma2(r.y, w2, o2[1]);
    }
    float o[4];
    upk2(o2[0], o[0], o[1]);
    upk2(o2[1], o[2], o[3]);

    // ---- scatter: +msg to dst, -msg to src (fixed edge: + to dst only)
    float* yd = xnxt + (long)d * NODE_STRIDE;
    float* ys = xnxt + (long)s * NODE_STRIDE;
    #pragma unroll
    for (int j = 0; j < 4; j++) {
        const int b = bg * 4 + j;
        atomicAdd(yd + b * FF + f, o[j]);
        if (!fx) atomicAdd(ys + b * FF + f, -o[j]);
    }
}

// ---------------------------------------------------------------------------
extern "C" void kernel_launch(void* const* d_in, const int* in_sizes, int n_in,
                              void* d_out, int out_size) {
    const float* h     = (const float*)d_in[0];
    const float* Wi0   = (const float*)d_in[1];
    const float* Wih   = (const float*)d_in[2];
    const float* Wiout = (const float*)d_in[3];
    const float* bi0   = (const float*)d_in[4];
    const float* bih   = (const float*)d_in[5];
    const float* biout = (const float*)d_in[6];
    const float* Wf0   = (const float*)d_in[7];
    const float* Wfh   = (const float*)d_in[8];
    const float* Wfout = (const float*)d_in[9];
    const float* bf0   = (const float*)d_in[10];
    const float* bfh   = (const float*)d_in[11];
    const float* bfout = (const float*)d_in[12];
    const int*   src   = (const int*)d_in[13];
    const int*   dst   = (const int*)d_in[14];
    float*       out   = (float*)d_out;

    const int tb = 256;
    const int pblocks = (NN * BB + tb - 1) / tb;
    const int eblocks = (PP + 1 + WPB - 1) / WPB;

    dummy_kernel<<<1, 32>>>();   // aligns ncu's profiled slot onto edge_kernel(layer1)

    prep_kernel<<<pblocks, tb>>>(h);

    edge_kernel<<<eblocks, WPB * 32>>>(Wi0, Wih, Wiout, bi0, bih, biout,
                                       Wf0, Wfh, Wfout, bf0, bfh, bfout,
                                       src, dst, /*layer=*/0, /*cur=*/0, /*nxt=*/1);

    edge_kernel<<<eblocks, WPB * 32>>>(Wi0, Wih, Wiout, bi0, bih, biout,
                                       Wf0, Wfh, Wfout, bf0, bfh, bfout,
                                       src, dst, /*layer=*/1, /*cur=*/1, /*nxt=*/2);

    out_kernel<<<pblocks, tb>>>(out);
}

// round 4
// speedup vs baseline: 1.5028x; 1.1151x over previous
#include <cuda_runtime.h>
#include <math.h>

// Problem constants (fixed by the dataset)
#define NN 10000   // nodes
#define PP 25000   // edge-pairs
#define BB 8       // batch
#define FF 16      // feats
#define MM 32      // MLP width
#define HH 2       // MLP hidden layers
#define TWO_F (2*FF)          // 32
#define NODE_STRIDE (BB*FF)   // 128 floats per node
#define XELEMS (NN*NODE_STRIDE)

// triple node-state buffers, [N][B][F] layout (layer0: 0->1, layer1: 1->2)
__device__ __align__(16) float g_x[3][XELEMS];

// ---------------------------------------------------------------------------
// f32x2 packed-math helpers (sm_103a)
__device__ __forceinline__ unsigned long long pk2(float x, float y) {
    unsigned long long r;
    asm("mov.b64 %0,{%1,%2};" : "=l"(r) : "f"(x), "f"(y));
    return r;
}
__device__ __forceinline__ void upk2(unsigned long long v, float& x, float& y) {
    asm("mov.b64 {%0,%1},%2;" : "=f"(x), "=f"(y) : "l"(v));
}
__device__ __forceinline__ unsigned long long fma2(unsigned long long a,
                                                   unsigned long long b,
                                                   unsigned long long c) {
    unsigned long long d;
    asm("fma.rn.f32x2 %0,%1,%2,%3;" : "=l"(d) : "l"(a), "l"(b), "l"(c));
    return d;
}
// fast silu: MUFU.EX2 + MUFU.RCP, no full-precision division refinement
__device__ __forceinline__ float silu_f(float v) {
    return __fdividef(v, 1.0f + __expf(-v));
}

// ---------------------------------------------------------------------------
// profiler-alignment dummy (places edge_kernel at profiled launch slot)
__global__ void dummy_kernel() {}

// prep: h [B][N][F] -> g_x[0] [N][B][F]; zero g_x[1], g_x[2].
__global__ void prep_kernel(const float* __restrict__ h) {
    int idx = blockIdx.x * blockDim.x + threadIdx.x;
    if (idx >= NN * BB) return;
    int b = idx / NN;
    int n = idx - b * NN;
    const float4* s  = (const float4*)(h + (size_t)b * NN * FF + (size_t)n * FF);
    float4* d0 = (float4*)(g_x[0] + (size_t)n * NODE_STRIDE + b * FF);
    float4* d1 = (float4*)(g_x[1] + (size_t)n * NODE_STRIDE + b * FF);
    float4* d2 = (float4*)(g_x[2] + (size_t)n * NODE_STRIDE + b * FF);
    const float4 z = make_float4(0.f, 0.f, 0.f, 0.f);
    #pragma unroll
    for (int j = 0; j < 4; j++) { d0[j] = s[j]; d1[j] = z; d2[j] = z; }
}

// g_x[2] [N][B][F] -> out [B][N][F]
__global__ void out_kernel(float* __restrict__ out) {
    int idx = blockIdx.x * blockDim.x + threadIdx.x;
    if (idx >= NN * BB) return;
    int b = idx / NN;
    int n = idx - b * NN;
    const float4* s = (const float4*)(g_x[2] + (size_t)n * NODE_STRIDE + b * FF);
    float4* d = (float4*)(out + (size_t)b * NN * FF + (size_t)n * FF);
    #pragma unroll
    for (int j = 0; j < 4; j++) d[j] = s[j];
}

// ---------------------------------------------------------------------------
// One warp per edge-pair. Activations in k-major smem [k][b]; FMA loop reads
// row k (uniform broadcast LDS.128) as 4 packed f32x2 operands; lane m owns
// output column m with 4 packed batch-pair accumulators. Weight loads stay
// interleaved (32 coalesced 128B LDG.32 per layer).
#define WPB 4  // warps per block (small blocks -> 10 blocks/SM at <=51 regs)

// one MLP layer: [B,32] @ [32,32] + bias + silu, k-major in/out
__device__ __forceinline__ void mlp32_layer(const float* __restrict__ W,
                                            const float* __restrict__ bias,
                                            const float (*cur)[BB],
                                            float (*nxt)[BB],
                                            int lane)
{
    const float bv = bias[lane];
    unsigned long long acc2[4];
    #pragma unroll
    for (int j = 0; j < 4; j++) acc2[j] = pk2(bv, bv);
    #pragma unroll
    for (int k = 0; k < MM; k++) {
        const float w = W[k * MM + lane];
        const unsigned long long w2 = pk2(w, w);
        const ulonglong2* row = (const ulonglong2*)cur[k];
        const ulonglong2 r0 = row[0];
        const ulonglong2 r1 = row[1];
        acc2[0] = fma2(r0.x, w2, acc2[0]);
        acc2[1] = fma2(r0.y, w2, acc2[1]);
        acc2[2] = fma2(r1.x, w2, acc2[2]);
        acc2[3] = fma2(r1.y, w2, acc2[3]);
    }
    float s[8];
    #pragma unroll
    for (int j = 0; j < 4; j++) {
        float a, b;
        upk2(acc2[j], a, b);
        s[2 * j]     = silu_f(a);
        s[2 * j + 1] = silu_f(b);
    }
    *(float4*)&nxt[lane][0] = make_float4(s[0], s[1], s[2], s[3]);
    *(float4*)&nxt[lane][4] = make_float4(s[4], s[5], s[6], s[7]);
}

// All weight/bias pointers are PRE-OFFSET to the current GNN layer on host.
__global__ void __launch_bounds__(WPB * 32, 10)
edge_kernel(const float* __restrict__ Wi0,  const float* __restrict__ Wih,
            const float* __restrict__ Wiout,const float* __restrict__ bi0,
            const float* __restrict__ bih,  const float* __restrict__ biout,
            const float* __restrict__ Wf0,  const float* __restrict__ Wfh,
            const float* __restrict__ Wfout,const float* __restrict__ bf0,
            const float* __restrict__ bfh,  const float* __restrict__ bfout,
            const int* __restrict__ src,    const int* __restrict__ dst,
            int curbuf, int nxtbuf)
{
    // k-major double-buffered activations: [warp][pp][k][b]
    __shared__ __align__(16) float smX[WPB][2][MM][BB];

    const int w    = threadIdx.x >> 5;
    const int lane = threadIdx.x & 31;
    const int e    = blockIdx.x * WPB + w;
    if (e > PP) return;

    const bool fx   = (e == PP);
    const int  eidx = fx ? 2 * PP : e;   // fixed edge is the last entry
    const int  d = dst[eidx];
    const int  s = src[eidx];

    const int Pp = fx ? 1 : PP;
    const int pe = fx ? 0 : e;

    const float* W0   = (fx ? Wf0   : Wi0)   + (size_t)pe * (TWO_F * MM);
    const float* b0   = (fx ? bf0   : bi0)   + (size_t)pe * MM;
    const float* Wout = (fx ? Wfout : Wiout) + (size_t)pe * (MM * FF);
    const float* bout = (fx ? bfout : biout) + (size_t)pe * FF;
    const float* WhB  = fx ? Wfh : Wih;
    const float* bhB  = fx ? bfh : bih;

    const float* xcur = g_x[curbuf];
    float*       xnxt = g_x[nxtbuf];

    // ---- gather edge input into k-major smem: lane = k of [x_dst | x_src]
    {
        const float* xd = xcur + (size_t)d * NODE_STRIDE;
        const float* xs = xcur + (size_t)s * NODE_STRIDE;
        const float* xg = (lane < FF) ? xd : xs;
        const int f0 = lane & 15;
        float v[BB];
        #pragma unroll
        for (int b = 0; b < BB; b++) v[b] = xg[b * FF + f0];
        *(float4*)&smX[w][0][lane][0] = make_float4(v[0], v[1], v[2], v[3]);
        *(float4*)&smX[w][0][lane][4] = make_float4(v[4], v[5], v[6], v[7]);
    }
    __syncwarp();

    // ---- layer 0 + hidden layers (all 32 -> 32)
    mlp32_layer(W0, b0, smX[w][0], smX[w][1], lane);
    __syncwarp();
    int cur = 1;
    #pragma unroll
    for (int i = 0; i < HH; i++) {
        const float* Wh = WhB + ((size_t)i * Pp + pe) * (MM * MM);
        const float* bh = bhB + ((size_t)i * Pp + pe) * MM;
        mlp32_layer(Wh, bh, smX[w][cur], smX[w][cur ^ 1], lane);
        __syncwarp();
        cur ^= 1;
    }

    // ---- output layer: [B,32] @ [32,16]; lanes 0-15 -> batches 0-3, 16-31 -> 4-7
    const int f  = lane & 15;
    const int bg = lane >> 4;
    const float ob = bout[f];
    unsigned long long o2[2] = { pk2(ob, ob), pk2(ob, ob) };
    const float (*A)[BB] = smX[w][cur];
    #pragma unroll
    for (int k = 0; k < MM; k++) {
        const float wv = Wout[k * FF + f];
        const unsigned long long w2 = pk2(wv, wv);
        const ulonglong2 r = *(const ulonglong2*)&A[k][bg * 4];
        o2[0] = fma2(r.x, w2, o2[0]);
        o2[1] = fma2(r.y, w2, o2[1]);
    }
    float o[4];
    upk2(o2[0], o[0], o[1]);
    upk2(o2[1], o[2], o[3]);

    // ---- scatter: +msg to dst, -msg to src (fixed edge: + to dst only)
    float* yd = xnxt + (size_t)d * NODE_STRIDE;
    float* ys = xnxt + (size_t)s * NODE_STRIDE;
    #pragma unroll
    for (int j = 0; j < 4; j++) {
        const int b = bg * 4 + j;
        atomicAdd(yd + b * FF + f, o[j]);
        if (!fx) atomicAdd(ys + b * FF + f, -o[j]);
    }
}

// ---------------------------------------------------------------------------
extern "C" void kernel_launch(void* const* d_in, const int* in_sizes, int n_in,
                              void* d_out, int out_size) {
    const float* h     = (const float*)d_in[0];
    const float* Wi0   = (const float*)d_in[1];
    const float* Wih   = (const float*)d_in[2];
    const float* Wiout = (const float*)d_in[3];
    const float* bi0   = (const float*)d_in[4];
    const float* bih   = (const float*)d_in[5];
    const float* biout = (const float*)d_in[6];
    const float* Wf0   = (const float*)d_in[7];
    const float* Wfh   = (const float*)d_in[8];
    const float* Wfout = (const float*)d_in[9];
    const float* bf0   = (const float*)d_in[10];
    const float* bfh   = (const float*)d_in[11];
    const float* bfout = (const float*)d_in[12];
    const int*   src   = (const int*)d_in[13];
    const int*   dst   = (const int*)d_in[14];
    float*       out   = (float*)d_out;

    const int tb = 256;
    const int pblocks = (NN * BB + tb - 1) / tb;
    const int eblocks = (PP + 1 + WPB - 1) / WPB;

    dummy_kernel<<<1, 32>>>();   // keeps ncu's profiled slot on edge_kernel(layer1)

    prep_kernel<<<pblocks, tb>>>(h);

    // layer 0 (host pre-offsets all layer bases)
    edge_kernel<<<eblocks, WPB * 32>>>(
        Wi0, Wih, Wiout, bi0, bih, biout,
        Wf0, Wfh, Wfout, bf0, bfh, bfout,
        src, dst, 0, 1);

    // layer 1
    edge_kernel<<<eblocks, WPB * 32>>>(
        Wi0   + (size_t)PP * TWO_F * MM,
        Wih   + (size_t)HH * PP * MM * MM,
        Wiout + (size_t)PP * MM * FF,
        bi0   + (size_t)PP * MM,
        bih   + (size_t)HH * PP * MM,
        biout + (size_t)PP * FF,
        Wf0   + (size_t)TWO_F * MM,
        Wfh   + (size_t)HH * MM * MM,
        Wfout + (size_t)MM * FF,
        bf0   + (size_t)MM,
        bfh   + (size_t)HH * MM,
        bfout + (size_t)FF,
        src, dst, 1, 2);

    out_kernel<<<pblocks, tb>>>(out);
}